// round 3
// baseline (speedup 1.0000x reference)
#include <cuda_runtime.h>
#include <math.h>
#include <stdint.h>

// Problem constants
#define SQ   2048      // sequence length
#define DH   64        // head dim
#define NBH  64        // B*H
#define TQ   64        // q rows per CTA
#define TK   64        // k cols per tile
#define NTHR 256
#define NKT  (SQ / TK) // 32 k tiles
#define QPAD 68        // padded row (floats) for Q/K tiles (conflict-free f4)
#define PPAD 65        // padded row for P tile

// Smem layout (floats):
//   Qs: TQ x QPAD   = 4352
//   Ks: TK x QPAD   = 4352
//   Vs: TK x DH     = 4096
//   Ps: TQ x PPAD   = 4160
// total = 16960 floats = 67840 bytes (dynamic smem)
#define SMEM_FLOATS (TQ*QPAD + TK*QPAD + TK*DH + TQ*PPAD)

__device__ __forceinline__ float rmax16(float v) {
    v = fmaxf(v, __shfl_xor_sync(0xffffffffu, v, 1));
    v = fmaxf(v, __shfl_xor_sync(0xffffffffu, v, 2));
    v = fmaxf(v, __shfl_xor_sync(0xffffffffu, v, 4));
    v = fmaxf(v, __shfl_xor_sync(0xffffffffu, v, 8));
    return v;
}
__device__ __forceinline__ float rsum16(float v) {
    v += __shfl_xor_sync(0xffffffffu, v, 1);
    v += __shfl_xor_sync(0xffffffffu, v, 2);
    v += __shfl_xor_sync(0xffffffffu, v, 4);
    v += __shfl_xor_sync(0xffffffffu, v, 8);
    return v;
}

// Compute 4x4 score block: acc[ii][jj] = sum_d Q[rg*4+ii][d] * K[c4+16*jj][d]
__device__ __forceinline__ void compute_scores(
    const float* __restrict__ Qs, const float* __restrict__ Ks,
    int rg, int c4, float acc[4][4])
{
#pragma unroll
    for (int ii = 0; ii < 4; ++ii)
#pragma unroll
        for (int jj = 0; jj < 4; ++jj) acc[ii][jj] = 0.0f;

#pragma unroll
    for (int d4 = 0; d4 < DH / 4; ++d4) {
        float4 qv[4], kv[4];
#pragma unroll
        for (int ii = 0; ii < 4; ++ii)
            qv[ii] = ((const float4*)(Qs + (rg * 4 + ii) * QPAD))[d4];
#pragma unroll
        for (int jj = 0; jj < 4; ++jj)
            kv[jj] = ((const float4*)(Ks + (c4 + 16 * jj) * QPAD))[d4];
#pragma unroll
        for (int ii = 0; ii < 4; ++ii) {
#pragma unroll
            for (int jj = 0; jj < 4; ++jj) {
                acc[ii][jj] = fmaf(qv[ii].x, kv[jj].x, acc[ii][jj]);
                acc[ii][jj] = fmaf(qv[ii].y, kv[jj].y, acc[ii][jj]);
                acc[ii][jj] = fmaf(qv[ii].z, kv[jj].z, acc[ii][jj]);
                acc[ii][jj] = fmaf(qv[ii].w, kv[jj].w, acc[ii][jj]);
            }
        }
    }
}

__global__ void __launch_bounds__(NTHR)
sdpa_kernel(const float* __restrict__ Qg, const float* __restrict__ Kg,
            const float* __restrict__ Vg,
            float* __restrict__ ctx_out, float* __restrict__ attn_out)
{
    extern __shared__ float sm[];
    float* Qs = sm;
    float* Ks = Qs + TQ * QPAD;
    float* Vs = Ks + TK * QPAD;
    float* Ps = Vs + TK * DH;

    const int tid = threadIdx.x;
    const int bh  = blockIdx.x >> 5;   // 32 q-tiles per (b,h)
    const int qt  = blockIdx.x & 31;
    const int q0  = qt * TQ;

    const int rg = tid >> 4;  // 0..15 : owns rows rg*4 .. rg*4+3
    const int c4 = tid & 15;  // 0..15 : owns cols c4 + 16*jj  and d-slice c4*4..c4*4+3

    const size_t base = (size_t)bh * SQ * DH;  // float offset of this head
    const float4* Qg4 = (const float4*)(Qg + base);
    const float4* Kg4 = (const float4*)(Kg + base);
    const float4* Vg4 = (const float4*)(Vg + base);

    // ---- load Q tile (64 x 64 floats = 1024 f4) ----
#pragma unroll
    for (int i = 0; i < 4; ++i) {
        int idx = tid + NTHR * i;
        int row = idx >> 4, col = idx & 15;
        ((float4*)(Qs + row * QPAD))[col] = Qg4[(size_t)(q0 + row) * (DH / 4) + col];
    }

    float m_run[4], Zf[4], Zc[4];
#pragma unroll
    for (int ii = 0; ii < 4; ++ii) { m_run[ii] = -INFINITY; Zf[ii] = 0.0f; Zc[ii] = 0.0f; }

    // ================= Phase 1: full-row softmax stats =================
    for (int kt = 0; kt < NKT; ++kt) {
        __syncthreads();
#pragma unroll
        for (int i = 0; i < 4; ++i) {
            int idx = tid + NTHR * i;
            int row = idx >> 4, col = idx & 15;
            ((float4*)(Ks + row * QPAD))[col] = Kg4[(size_t)(kt * TK + row) * (DH / 4) + col];
        }
        __syncthreads();

        float acc[4][4];
        compute_scores(Qs, Ks, rg, c4, acc);

#pragma unroll
        for (int ii = 0; ii < 4; ++ii) {
            const int q = q0 + rg * 4 + ii;
            float s[4], tmax = -INFINITY;
#pragma unroll
            for (int jj = 0; jj < 4; ++jj) {
                s[jj] = acc[ii][jj] * 0.125f;   // 1/sqrt(64)
                tmax = fmaxf(tmax, s[jj]);
            }
            tmax = rmax16(tmax);
            const float mnew = fmaxf(m_run[ii], tmax);
            float se = 0.0f, sec = 0.0f;
#pragma unroll
            for (int jj = 0; jj < 4; ++jj) {
                float e = __expf(s[jj] - mnew);
                se += e;
                int kg = kt * TK + c4 + 16 * jj;
                if (kg <= q) sec += e;
            }
            se  = rsum16(se);
            sec = rsum16(sec);
            const float scl = __expf(m_run[ii] - mnew);
            Zf[ii] = Zf[ii] * scl + se;
            Zc[ii] = Zc[ii] * scl + sec;
            m_run[ii] = mnew;
        }
    }

    float invD[4];
#pragma unroll
    for (int ii = 0; ii < 4; ++ii)
        invD[ii] = 1.0f / (Zc[ii] + 1e-8f * Zf[ii]);

    // ================= Phase 2: attn output + context =================
    float4 ctx[4];
#pragma unroll
    for (int ii = 0; ii < 4; ++ii) ctx[ii] = make_float4(0.f, 0.f, 0.f, 0.f);

    const size_t attn_row0 = ((size_t)bh * SQ + q0) * SQ;  // float index of (bh, q0, 0)

    for (int kt = 0; kt <= qt; ++kt) {   // only tiles that intersect the causal region
        __syncthreads();
#pragma unroll
        for (int i = 0; i < 4; ++i) {
            int idx = tid + NTHR * i;
            int row = idx >> 4, col = idx & 15;
            size_t g = (size_t)(kt * TK + row) * (DH / 4) + col;
            ((float4*)(Ks + row * QPAD))[col] = Kg4[g];
            ((float4*)(Vs + row * DH))[col]   = Vg4[g];
        }
        __syncthreads();

        float acc[4][4];
        compute_scores(Qs, Ks, rg, c4, acc);

#pragma unroll
        for (int ii = 0; ii < 4; ++ii) {
            const int q = q0 + rg * 4 + ii;
#pragma unroll
            for (int jj = 0; jj < 4; ++jj) {
                int kl = c4 + 16 * jj;
                int kg = kt * TK + kl;
                float p = (kg <= q) ? __expf(acc[ii][jj] * 0.125f - m_run[ii]) * invD[ii]
                                    : 0.0f;
                Ps[(rg * 4 + ii) * PPAD + kl] = p;
            }
        }
        __syncthreads();

        // coalesced attn store from P tile
        if (attn_out) {
#pragma unroll
            for (int i = 0; i < 4; ++i) {
                int idx = tid + NTHR * i;
                int row = idx >> 4, cc = idx & 15;
                float4 v;
                v.x = Ps[row * PPAD + cc * 4 + 0];
                v.y = Ps[row * PPAD + cc * 4 + 1];
                v.z = Ps[row * PPAD + cc * 4 + 2];
                v.w = Ps[row * PPAD + cc * 4 + 3];
                ((float4*)(attn_out + attn_row0 + (size_t)row * SQ + kt * TK))[cc] = v;
            }
        }

        // P @ V accumulation: thread owns (4 rows) x (d = c4*4 .. c4*4+3)
#pragma unroll 4
        for (int k = 0; k < TK; ++k) {
            float4 vv = ((const float4*)(Vs + k * DH))[c4];
#pragma unroll
            for (int ii = 0; ii < 4; ++ii) {
                float p = Ps[(rg * 4 + ii) * PPAD + k];
                ctx[ii].x = fmaf(p, vv.x, ctx[ii].x);
                ctx[ii].y = fmaf(p, vv.y, ctx[ii].y);
                ctx[ii].z = fmaf(p, vv.z, ctx[ii].z);
                ctx[ii].w = fmaf(p, vv.w, ctx[ii].w);
            }
        }
    }

    // zero-fill strictly-upper tiles of attn (output was poisoned)
    if (attn_out) {
        const float4 z = make_float4(0.f, 0.f, 0.f, 0.f);
        for (int kt = qt + 1; kt < NKT; ++kt) {
#pragma unroll
            for (int i = 0; i < 4; ++i) {
                int idx = tid + NTHR * i;
                int row = idx >> 4, cc = idx & 15;
                ((float4*)(attn_out + attn_row0 + (size_t)row * SQ + kt * TK))[cc] = z;
            }
        }
    }

    if (ctx_out) {
#pragma unroll
        for (int ii = 0; ii < 4; ++ii) {
            int row = rg * 4 + ii;
            ((float4*)(ctx_out + ((size_t)bh * SQ + q0 + row) * DH))[c4] = ctx[ii];
        }
    }
}

extern "C" void kernel_launch(void* const* d_in, const int* in_sizes, int n_in,
                              void* d_out, int out_size)
{
    const float* Q = (const float*)d_in[0];
    const float* K = (const float*)d_in[1];
    const float* V = (const float*)d_in[2];
    // d_in[3] = attn_mask (tril, deterministic causal) — handled analytically
    // d_in[4] = d_k (= 64)

    float* out = (float*)d_out;
    const long long CTX = (long long)NBH * SQ * DH;       // 8388608
    const long long ATT = (long long)NBH * SQ * SQ;       // 268435456

    float* ctx_out  = nullptr;
    float* attn_out = nullptr;
    long long osz = (long long)out_size;
    if (osz >= CTX + ATT) {            // (context, attn) concatenated
        ctx_out  = out;
        attn_out = out + CTX;
    } else if (osz >= ATT) {           // attn only
        attn_out = out;
    } else {                           // context only
        ctx_out = out;
    }

    const int smem_bytes = SMEM_FLOATS * (int)sizeof(float);
    cudaFuncSetAttribute(sdpa_kernel, cudaFuncAttributeMaxDynamicSharedMemorySize,
                         smem_bytes);

    dim3 grid(NBH * (SQ / TQ));   // 2048 CTAs
    dim3 block(NTHR);
    sdpa_kernel<<<grid, block, smem_bytes>>>(Q, K, V, ctx_out, attn_out);
}

// round 4
// speedup vs baseline: 1.0037x; 1.0037x over previous
#include <cuda_runtime.h>
#include <math.h>
#include <stdint.h>

// Problem constants
#define SQ   2048      // sequence length
#define DH   64        // head dim
#define NBH  64        // B*H
#define TQ   64        // q rows per CTA
#define TK   64        // k cols per tile
#define NTHR 256
#define NKT  (SQ / TK) // 32 k tiles
#define QPAD 68        // padded row (floats) for Q/K tiles (conflict-free f4)
#define PPAD 65        // padded row for P tile

// Smem layout (floats):
//   Qs: TQ x QPAD   = 4352
//   Ks: TK x QPAD   = 4352
//   Vs: TK x DH     = 4096
//   Ps: TQ x PPAD   = 4160
// total = 16960 floats = 67840 bytes (dynamic smem)
#define SMEM_FLOATS (TQ*QPAD + TK*QPAD + TK*DH + TQ*PPAD)

__device__ __forceinline__ float rmax16(float v) {
    v = fmaxf(v, __shfl_xor_sync(0xffffffffu, v, 1));
    v = fmaxf(v, __shfl_xor_sync(0xffffffffu, v, 2));
    v = fmaxf(v, __shfl_xor_sync(0xffffffffu, v, 4));
    v = fmaxf(v, __shfl_xor_sync(0xffffffffu, v, 8));
    return v;
}
__device__ __forceinline__ float rsum16(float v) {
    v += __shfl_xor_sync(0xffffffffu, v, 1);
    v += __shfl_xor_sync(0xffffffffu, v, 2);
    v += __shfl_xor_sync(0xffffffffu, v, 4);
    v += __shfl_xor_sync(0xffffffffu, v, 8);
    return v;
}

// Compute 4x4 score block: acc[ii][jj] = sum_d Q[rg*4+ii][d] * K[c4+16*jj][d]
__device__ __forceinline__ void compute_scores(
    const float* __restrict__ Qs, const float* __restrict__ Ks,
    int rg, int c4, float acc[4][4])
{
#pragma unroll
    for (int ii = 0; ii < 4; ++ii)
#pragma unroll
        for (int jj = 0; jj < 4; ++jj) acc[ii][jj] = 0.0f;

#pragma unroll
    for (int d4 = 0; d4 < DH / 4; ++d4) {
        float4 qv[4], kv[4];
#pragma unroll
        for (int ii = 0; ii < 4; ++ii)
            qv[ii] = ((const float4*)(Qs + (rg * 4 + ii) * QPAD))[d4];
#pragma unroll
        for (int jj = 0; jj < 4; ++jj)
            kv[jj] = ((const float4*)(Ks + (c4 + 16 * jj) * QPAD))[d4];
#pragma unroll
        for (int ii = 0; ii < 4; ++ii) {
#pragma unroll
            for (int jj = 0; jj < 4; ++jj) {
                acc[ii][jj] = fmaf(qv[ii].x, kv[jj].x, acc[ii][jj]);
                acc[ii][jj] = fmaf(qv[ii].y, kv[jj].y, acc[ii][jj]);
                acc[ii][jj] = fmaf(qv[ii].z, kv[jj].z, acc[ii][jj]);
                acc[ii][jj] = fmaf(qv[ii].w, kv[jj].w, acc[ii][jj]);
            }
        }
    }
}

__global__ void __launch_bounds__(NTHR)
sdpa_kernel(const float* __restrict__ Qg, const float* __restrict__ Kg,
            const float* __restrict__ Vg,
            float* __restrict__ ctx_out, float* __restrict__ attn_out)
{
    extern __shared__ float sm[];
    float* Qs = sm;
    float* Ks = Qs + TQ * QPAD;
    float* Vs = Ks + TK * QPAD;
    float* Ps = Vs + TK * DH;

    const int tid = threadIdx.x;
    const int bh  = blockIdx.x >> 5;   // 32 q-tiles per (b,h)
    const int qt  = blockIdx.x & 31;
    const int q0  = qt * TQ;

    const int rg = tid >> 4;  // 0..15 : owns rows rg*4 .. rg*4+3
    const int c4 = tid & 15;  // 0..15 : owns cols c4 + 16*jj  and d-slice c4*4..c4*4+3

    const size_t base = (size_t)bh * SQ * DH;  // float offset of this head
    const float4* Qg4 = (const float4*)(Qg + base);
    const float4* Kg4 = (const float4*)(Kg + base);
    const float4* Vg4 = (const float4*)(Vg + base);

    // ---- load Q tile (64 x 64 floats = 1024 f4) ----
#pragma unroll
    for (int i = 0; i < 4; ++i) {
        int idx = tid + NTHR * i;
        int row = idx >> 4, col = idx & 15;
        ((float4*)(Qs + row * QPAD))[col] = Qg4[(size_t)(q0 + row) * (DH / 4) + col];
    }

    float m_run[4], Zf[4], Zc[4];
#pragma unroll
    for (int ii = 0; ii < 4; ++ii) { m_run[ii] = -INFINITY; Zf[ii] = 0.0f; Zc[ii] = 0.0f; }

    // ================= Phase 1: full-row softmax stats =================
    for (int kt = 0; kt < NKT; ++kt) {
        __syncthreads();
#pragma unroll
        for (int i = 0; i < 4; ++i) {
            int idx = tid + NTHR * i;
            int row = idx >> 4, col = idx & 15;
            ((float4*)(Ks + row * QPAD))[col] = Kg4[(size_t)(kt * TK + row) * (DH / 4) + col];
        }
        __syncthreads();

        float acc[4][4];
        compute_scores(Qs, Ks, rg, c4, acc);

#pragma unroll
        for (int ii = 0; ii < 4; ++ii) {
            const int q = q0 + rg * 4 + ii;
            float s[4], tmax = -INFINITY;
#pragma unroll
            for (int jj = 0; jj < 4; ++jj) {
                s[jj] = acc[ii][jj] * 0.125f;   // 1/sqrt(64)
                tmax = fmaxf(tmax, s[jj]);
            }
            tmax = rmax16(tmax);
            const float mnew = fmaxf(m_run[ii], tmax);
            float se = 0.0f, sec = 0.0f;
#pragma unroll
            for (int jj = 0; jj < 4; ++jj) {
                float e = __expf(s[jj] - mnew);
                se += e;
                int kg = kt * TK + c4 + 16 * jj;
                if (kg <= q) sec += e;
            }
            se  = rsum16(se);
            sec = rsum16(sec);
            const float scl = __expf(m_run[ii] - mnew);
            Zf[ii] = Zf[ii] * scl + se;
            Zc[ii] = Zc[ii] * scl + sec;
            m_run[ii] = mnew;
        }
    }

    float invD[4];
#pragma unroll
    for (int ii = 0; ii < 4; ++ii)
        invD[ii] = 1.0f / (Zc[ii] + 1e-8f * Zf[ii]);

    // ================= Phase 2: attn output + context =================
    float4 ctx[4];
#pragma unroll
    for (int ii = 0; ii < 4; ++ii) ctx[ii] = make_float4(0.f, 0.f, 0.f, 0.f);

    const size_t attn_row0 = ((size_t)bh * SQ + q0) * SQ;  // float index of (bh, q0, 0)

    for (int kt = 0; kt <= qt; ++kt) {   // only tiles that intersect the causal region
        __syncthreads();
#pragma unroll
        for (int i = 0; i < 4; ++i) {
            int idx = tid + NTHR * i;
            int row = idx >> 4, col = idx & 15;
            size_t g = (size_t)(kt * TK + row) * (DH / 4) + col;
            ((float4*)(Ks + row * QPAD))[col] = Kg4[g];
            ((float4*)(Vs + row * DH))[col]   = Vg4[g];
        }
        __syncthreads();

        float acc[4][4];
        compute_scores(Qs, Ks, rg, c4, acc);

#pragma unroll
        for (int ii = 0; ii < 4; ++ii) {
            const int q = q0 + rg * 4 + ii;
#pragma unroll
            for (int jj = 0; jj < 4; ++jj) {
                int kl = c4 + 16 * jj;
                int kg = kt * TK + kl;
                float p = (kg <= q) ? __expf(acc[ii][jj] * 0.125f - m_run[ii]) * invD[ii]
                                    : 0.0f;
                Ps[(rg * 4 + ii) * PPAD + kl] = p;
            }
        }
        __syncthreads();

        // coalesced attn store from P tile
        if (attn_out) {
#pragma unroll
            for (int i = 0; i < 4; ++i) {
                int idx = tid + NTHR * i;
                int row = idx >> 4, cc = idx & 15;
                float4 v;
                v.x = Ps[row * PPAD + cc * 4 + 0];
                v.y = Ps[row * PPAD + cc * 4 + 1];
                v.z = Ps[row * PPAD + cc * 4 + 2];
                v.w = Ps[row * PPAD + cc * 4 + 3];
                ((float4*)(attn_out + attn_row0 + (size_t)row * SQ + kt * TK))[cc] = v;
            }
        }

        // P @ V accumulation: thread owns (4 rows) x (d = c4*4 .. c4*4+3)
#pragma unroll 4
        for (int k = 0; k < TK; ++k) {
            float4 vv = ((const float4*)(Vs + k * DH))[c4];
#pragma unroll
            for (int ii = 0; ii < 4; ++ii) {
                float p = Ps[(rg * 4 + ii) * PPAD + k];
                ctx[ii].x = fmaf(p, vv.x, ctx[ii].x);
                ctx[ii].y = fmaf(p, vv.y, ctx[ii].y);
                ctx[ii].z = fmaf(p, vv.z, ctx[ii].z);
                ctx[ii].w = fmaf(p, vv.w, ctx[ii].w);
            }
        }
    }

    // zero-fill strictly-upper tiles of attn (output was poisoned)
    if (attn_out) {
        const float4 z = make_float4(0.f, 0.f, 0.f, 0.f);
        for (int kt = qt + 1; kt < NKT; ++kt) {
#pragma unroll
            for (int i = 0; i < 4; ++i) {
                int idx = tid + NTHR * i;
                int row = idx >> 4, cc = idx & 15;
                ((float4*)(attn_out + attn_row0 + (size_t)row * SQ + kt * TK))[cc] = z;
            }
        }
    }

    if (ctx_out) {
#pragma unroll
        for (int ii = 0; ii < 4; ++ii) {
            int row = rg * 4 + ii;
            ((float4*)(ctx_out + ((size_t)bh * SQ + q0 + row) * DH))[c4] = ctx[ii];
        }
    }
}

extern "C" void kernel_launch(void* const* d_in, const int* in_sizes, int n_in,
                              void* d_out, int out_size)
{
    const float* Q = (const float*)d_in[0];
    const float* K = (const float*)d_in[1];
    const float* V = (const float*)d_in[2];
    // d_in[3] = attn_mask (tril, deterministic causal) — handled analytically
    // d_in[4] = d_k (= 64)

    float* out = (float*)d_out;
    const long long CTX = (long long)NBH * SQ * DH;       // 8388608
    const long long ATT = (long long)NBH * SQ * SQ;       // 268435456

    float* ctx_out  = nullptr;
    float* attn_out = nullptr;
    long long osz = (long long)out_size;
    if (osz >= CTX + ATT) {            // (context, attn) concatenated
        ctx_out  = out;
        attn_out = out + CTX;
    } else if (osz >= ATT) {           // attn only
        attn_out = out;
    } else {                           // context only
        ctx_out = out;
    }

    const int smem_bytes = SMEM_FLOATS * (int)sizeof(float);
    cudaFuncSetAttribute(sdpa_kernel, cudaFuncAttributeMaxDynamicSharedMemorySize,
                         smem_bytes);

    dim3 grid(NBH * (SQ / TQ));   // 2048 CTAs
    dim3 block(NTHR);
    sdpa_kernel<<<grid, block, smem_bytes>>>(Q, K, V, ctx_out, attn_out);
}

// round 7
// speedup vs baseline: 1.0089x; 1.0052x over previous
#include <cuda_runtime.h>
#include <math.h>
#include <stdint.h>

// Problem constants
#define SQ   2048      // sequence length
#define DH   64        // head dim
#define NBH  64        // B*H
#define TQ   64        // q rows per CTA
#define TK   64        // k cols per tile
#define NTHR 256
#define NKT  (SQ / TK) // 32 k tiles
#define QPAD 68        // padded row (floats) for Q/K tiles (conflict-free f4)
#define PPAD 65        // padded row for P tile

// Smem layout (floats):
//   Qs: TQ x QPAD   = 4352
//   Ks: TK x QPAD   = 4352
//   Vs: TK x DH     = 4096
//   Ps: TQ x PPAD   = 4160
// total = 16960 floats = 67840 bytes (dynamic smem)
#define SMEM_FLOATS (TQ*QPAD + TK*QPAD + TK*DH + TQ*PPAD)

__device__ __forceinline__ float rmax16(float v) {
    v = fmaxf(v, __shfl_xor_sync(0xffffffffu, v, 1));
    v = fmaxf(v, __shfl_xor_sync(0xffffffffu, v, 2));
    v = fmaxf(v, __shfl_xor_sync(0xffffffffu, v, 4));
    v = fmaxf(v, __shfl_xor_sync(0xffffffffu, v, 8));
    return v;
}
__device__ __forceinline__ float rsum16(float v) {
    v += __shfl_xor_sync(0xffffffffu, v, 1);
    v += __shfl_xor_sync(0xffffffffu, v, 2);
    v += __shfl_xor_sync(0xffffffffu, v, 4);
    v += __shfl_xor_sync(0xffffffffu, v, 8);
    return v;
}

// Compute 4x4 score block: acc[ii][jj] = sum_d Q[rg*4+ii][d] * K[c4+16*jj][d]
__device__ __forceinline__ void compute_scores(
    const float* __restrict__ Qs, const float* __restrict__ Ks,
    int rg, int c4, float acc[4][4])
{
#pragma unroll
    for (int ii = 0; ii < 4; ++ii)
#pragma unroll
        for (int jj = 0; jj < 4; ++jj) acc[ii][jj] = 0.0f;

#pragma unroll
    for (int d4 = 0; d4 < DH / 4; ++d4) {
        float4 qv[4], kv[4];
#pragma unroll
        for (int ii = 0; ii < 4; ++ii)
            qv[ii] = ((const float4*)(Qs + (rg * 4 + ii) * QPAD))[d4];
#pragma unroll
        for (int jj = 0; jj < 4; ++jj)
            kv[jj] = ((const float4*)(Ks + (c4 + 16 * jj) * QPAD))[d4];
#pragma unroll
        for (int ii = 0; ii < 4; ++ii) {
#pragma unroll
            for (int jj = 0; jj < 4; ++jj) {
                acc[ii][jj] = fmaf(qv[ii].x, kv[jj].x, acc[ii][jj]);
                acc[ii][jj] = fmaf(qv[ii].y, kv[jj].y, acc[ii][jj]);
                acc[ii][jj] = fmaf(qv[ii].z, kv[jj].z, acc[ii][jj]);
                acc[ii][jj] = fmaf(qv[ii].w, kv[jj].w, acc[ii][jj]);
            }
        }
    }
}

__global__ void __launch_bounds__(NTHR)
sdpa_kernel(const float* __restrict__ Qg, const float* __restrict__ Kg,
            const float* __restrict__ Vg,
            float* __restrict__ ctx_out, float* __restrict__ attn_out)
{
    extern __shared__ float sm[];
    float* Qs = sm;
    float* Ks = Qs + TQ * QPAD;
    float* Vs = Ks + TK * QPAD;
    float* Ps = Vs + TK * DH;

    const int tid = threadIdx.x;
    const int bh  = blockIdx.x >> 5;   // 32 q-tiles per (b,h)
    const int qt  = blockIdx.x & 31;
    const int q0  = qt * TQ;

    const int rg = tid >> 4;  // 0..15 : owns rows rg*4 .. rg*4+3
    const int c4 = tid & 15;  // 0..15 : owns cols c4 + 16*jj  and d-slice c4*4..c4*4+3

    const size_t base = (size_t)bh * SQ * DH;  // float offset of this head
    const float4* Qg4 = (const float4*)(Qg + base);
    const float4* Kg4 = (const float4*)(Kg + base);
    const float4* Vg4 = (const float4*)(Vg + base);

    // ---- load Q tile (64 x 64 floats = 1024 f4) ----
#pragma unroll
    for (int i = 0; i < 4; ++i) {
        int idx = tid + NTHR * i;
        int row = idx >> 4, col = idx & 15;
        ((float4*)(Qs + row * QPAD))[col] = Qg4[(size_t)(q0 + row) * (DH / 4) + col];
    }

    float m_run[4], Zf[4], Zc[4];
#pragma unroll
    for (int ii = 0; ii < 4; ++ii) { m_run[ii] = -INFINITY; Zf[ii] = 0.0f; Zc[ii] = 0.0f; }

    // ================= Phase 1: full-row softmax stats =================
    for (int kt = 0; kt < NKT; ++kt) {
        __syncthreads();
#pragma unroll
        for (int i = 0; i < 4; ++i) {
            int idx = tid + NTHR * i;
            int row = idx >> 4, col = idx & 15;
            ((float4*)(Ks + row * QPAD))[col] = Kg4[(size_t)(kt * TK + row) * (DH / 4) + col];
        }
        __syncthreads();

        float acc[4][4];
        compute_scores(Qs, Ks, rg, c4, acc);

#pragma unroll
        for (int ii = 0; ii < 4; ++ii) {
            const int q = q0 + rg * 4 + ii;
            float s[4], tmax = -INFINITY;
#pragma unroll
            for (int jj = 0; jj < 4; ++jj) {
                s[jj] = acc[ii][jj] * 0.125f;   // 1/sqrt(64)
                tmax = fmaxf(tmax, s[jj]);
            }
            tmax = rmax16(tmax);
            const float mnew = fmaxf(m_run[ii], tmax);
            float se = 0.0f, sec = 0.0f;
#pragma unroll
            for (int jj = 0; jj < 4; ++jj) {
                float e = __expf(s[jj] - mnew);
                se += e;
                int kg = kt * TK + c4 + 16 * jj;
                if (kg <= q) sec += e;
            }
            se  = rsum16(se);
            sec = rsum16(sec);
            const float scl = __expf(m_run[ii] - mnew);
            Zf[ii] = Zf[ii] * scl + se;
            Zc[ii] = Zc[ii] * scl + sec;
            m_run[ii] = mnew;
        }
    }

    float invD[4];
#pragma unroll
    for (int ii = 0; ii < 4; ++ii)
        invD[ii] = 1.0f / (Zc[ii] + 1e-8f * Zf[ii]);

    // ================= Phase 2: attn output + context =================
    float4 ctx[4];
#pragma unroll
    for (int ii = 0; ii < 4; ++ii) ctx[ii] = make_float4(0.f, 0.f, 0.f, 0.f);

    const size_t attn_row0 = ((size_t)bh * SQ + q0) * SQ;  // float index of (bh, q0, 0)

    for (int kt = 0; kt <= qt; ++kt) {   // only tiles that intersect the causal region
        __syncthreads();
#pragma unroll
        for (int i = 0; i < 4; ++i) {
            int idx = tid + NTHR * i;
            int row = idx >> 4, col = idx & 15;
            size_t g = (size_t)(kt * TK + row) * (DH / 4) + col;
            ((float4*)(Ks + row * QPAD))[col] = Kg4[g];
            ((float4*)(Vs + row * DH))[col]   = Vg4[g];
        }
        __syncthreads();

        float acc[4][4];
        compute_scores(Qs, Ks, rg, c4, acc);

#pragma unroll
        for (int ii = 0; ii < 4; ++ii) {
            const int q = q0 + rg * 4 + ii;
#pragma unroll
            for (int jj = 0; jj < 4; ++jj) {
                int kl = c4 + 16 * jj;
                int kg = kt * TK + kl;
                float p = (kg <= q) ? __expf(acc[ii][jj] * 0.125f - m_run[ii]) * invD[ii]
                                    : 0.0f;
                Ps[(rg * 4 + ii) * PPAD + kl] = p;
            }
        }
        __syncthreads();

        // coalesced attn store from P tile
        if (attn_out) {
#pragma unroll
            for (int i = 0; i < 4; ++i) {
                int idx = tid + NTHR * i;
                int row = idx >> 4, cc = idx & 15;
                float4 v;
                v.x = Ps[row * PPAD + cc * 4 + 0];
                v.y = Ps[row * PPAD + cc * 4 + 1];
                v.z = Ps[row * PPAD + cc * 4 + 2];
                v.w = Ps[row * PPAD + cc * 4 + 3];
                ((float4*)(attn_out + attn_row0 + (size_t)row * SQ + kt * TK))[cc] = v;
            }
        }

        // P @ V accumulation: thread owns (4 rows) x (d = c4*4 .. c4*4+3)
#pragma unroll 4
        for (int k = 0; k < TK; ++k) {
            float4 vv = ((const float4*)(Vs + k * DH))[c4];
#pragma unroll
            for (int ii = 0; ii < 4; ++ii) {
                float p = Ps[(rg * 4 + ii) * PPAD + k];
                ctx[ii].x = fmaf(p, vv.x, ctx[ii].x);
                ctx[ii].y = fmaf(p, vv.y, ctx[ii].y);
                ctx[ii].z = fmaf(p, vv.z, ctx[ii].z);
                ctx[ii].w = fmaf(p, vv.w, ctx[ii].w);
            }
        }
    }

    // zero-fill strictly-upper tiles of attn (output was poisoned)
    if (attn_out) {
        const float4 z = make_float4(0.f, 0.f, 0.f, 0.f);
        for (int kt = qt + 1; kt < NKT; ++kt) {
#pragma unroll
            for (int i = 0; i < 4; ++i) {
                int idx = tid + NTHR * i;
                int row = idx >> 4, cc = idx & 15;
                ((float4*)(attn_out + attn_row0 + (size_t)row * SQ + kt * TK))[cc] = z;
            }
        }
    }

    if (ctx_out) {
#pragma unroll
        for (int ii = 0; ii < 4; ++ii) {
            int row = rg * 4 + ii;
            ((float4*)(ctx_out + ((size_t)bh * SQ + q0 + row) * DH))[c4] = ctx[ii];
        }
    }
}

extern "C" void kernel_launch(void* const* d_in, const int* in_sizes, int n_in,
                              void* d_out, int out_size)
{
    const float* Q = (const float*)d_in[0];
    const float* K = (const float*)d_in[1];
    const float* V = (const float*)d_in[2];
    // d_in[3] = attn_mask (tril, deterministic causal) — handled analytically
    // d_in[4] = d_k (= 64)

    float* out = (float*)d_out;
    const long long CTX = (long long)NBH * SQ * DH;       // 8388608
    const long long ATT = (long long)NBH * SQ * SQ;       // 268435456

    float* ctx_out  = nullptr;
    float* attn_out = nullptr;
    long long osz = (long long)out_size;
    if (osz >= CTX + ATT) {            // (context, attn) concatenated
        ctx_out  = out;
        attn_out = out + CTX;
    } else if (osz >= ATT) {           // attn only
        attn_out = out;
    } else {                           // context only
        ctx_out = out;
    }

    const int smem_bytes = SMEM_FLOATS * (int)sizeof(float);
    cudaFuncSetAttribute(sdpa_kernel, cudaFuncAttributeMaxDynamicSharedMemorySize,
                         smem_bytes);

    dim3 grid(NBH * (SQ / TQ));   // 2048 CTAs
    dim3 block(NTHR);
    sdpa_kernel<<<grid, block, smem_bytes>>>(Q, K, V, ctx_out, attn_out);
}